// round 7
// baseline (speedup 1.0000x reference)
#include <cuda_runtime.h>

// Problem constants: B=4, N=512, E=64
#define NROWS 2048          // B*N
#define EDIM  64
#define CDIM  4096          // E*E

// Scratch (static device allocations are allowed)
__device__ float g_X[NROWS * EDIM];          // left gated activations  [row][d1]
__device__ float g_Y[NROWS * EDIM];          // right gated activations [row][d2]
__device__ float g_Wt[EDIM * CDIM];          // Wt[d1][d2*64+o] = Wc[o][d1*64+d2]
__device__ float g_T[NROWS * CDIM];          // T[row][d2*64+o]

// ---------------------------------------------------------------------------
// Stage A: LayerNorm + two gated projections. 1 block per row, 64 threads.
// ---------------------------------------------------------------------------
__global__ void prep_kernel(const float* __restrict__ emb,
                            const float* __restrict__ g,
                            const float* __restrict__ be,
                            const float* __restrict__ W1,
                            const float* __restrict__ b1,
                            const float* __restrict__ W2,
                            const float* __restrict__ b2)
{
    __shared__ float hsh[64];
    __shared__ float w1s[64 * 65];   // transposed [d][o], pad 65 -> conflict free
    __shared__ float w2s[64 * 65];

    const int row = blockIdx.x;
    const int t   = threadIdx.x;

    // Load weights transposed into shared (coalesced global reads).
    for (int i = 0; i < 64; i++) {
        w1s[t * 65 + i] = W1[i * 64 + t];   // w1s[d=t][o=i]
        w2s[t * 65 + i] = W2[i * 64 + t];
    }

    float v = emb[row * 64 + t];
    hsh[t] = v;
    __syncthreads();

    float s = 0.f;
    #pragma unroll
    for (int d = 0; d < 64; d++) s += hsh[d];
    float mu = s * (1.0f / 64.0f);

    float vs = 0.f;
    #pragma unroll
    for (int d = 0; d < 64; d++) { float z = hsh[d] - mu; vs += z * z; }
    float rstd = rsqrtf(vs * (1.0f / 64.0f) + 1e-5f);

    float h = (v - mu) * rstd * g[t] + be[t];
    __syncthreads();          // everyone done reading raw values
    hsh[t] = h;
    __syncthreads();

    float p1 = b1[t], p2 = b2[t];
    #pragma unroll
    for (int d = 0; d < 64; d++) {
        float hd = hsh[d];
        p1 += hd * w1s[d * 65 + t];
        p2 += hd * w2s[d * 65 + t];
    }
    g_X[row * 64 + t] = h * p1;
    g_Y[row * 64 + t] = h * p2;
}

// ---------------------------------------------------------------------------
// Stage C: transpose Wc into Wt[d1*4096 + d2*64 + o] = Wc[o*4096 + d1*64 + d2]
// ---------------------------------------------------------------------------
__global__ void wt_kernel(const float* __restrict__ Wc)
{
    int i = blockIdx.x * blockDim.x + threadIdx.x;   // 0 .. 262143
    int o    = i & 63;
    int rest = i >> 6;          // d1*64 + d2
    g_Wt[i] = Wc[o * 4096 + rest];
}

// ---------------------------------------------------------------------------
// Stage B: T = X @ Wt    ([2048 x 64] * [64 x 4096])
// Block tile 64 rows x 256 cols, 256 threads, 8x8 per thread.
// ---------------------------------------------------------------------------
__global__ void __launch_bounds__(256) t_kernel()
{
    extern __shared__ float smem[];
    float* xs = smem;             // [64 d1][65]  (rows transposed)
    float* ws = smem + 64 * 65;   // [64 d1][256]

    const int cb  = blockIdx.x;   // 0..15 (col block of 256)
    const int rb  = blockIdx.y;   // 0..31 (row block of 64)
    const int tid = threadIdx.x;

    // Load X tile transposed: xs[d1][r]
    #pragma unroll
    for (int it = 0; it < 4; it++) {
        int idx = it * 256 + tid;         // 0..1023 float4s
        int r   = idx >> 4;               // 0..63
        int c4  = idx & 15;
        float4 v = reinterpret_cast<const float4*>(g_X + (rb * 64 + r) * 64)[c4];
        xs[(4 * c4 + 0) * 65 + r] = v.x;
        xs[(4 * c4 + 1) * 65 + r] = v.y;
        xs[(4 * c4 + 2) * 65 + r] = v.z;
        xs[(4 * c4 + 3) * 65 + r] = v.w;
    }
    // Load W tile straight: ws[d1][c], 4096 float4s
    #pragma unroll
    for (int it = 0; it < 16; it++) {
        int idx = it * 256 + tid;         // 0..4095
        int d1  = idx >> 6;
        int c4  = idx & 63;
        reinterpret_cast<float4*>(ws + d1 * 256)[c4] =
            reinterpret_cast<const float4*>(g_Wt + d1 * 4096 + cb * 256)[c4];
    }
    __syncthreads();

    const int tx = tid & 31;   // col group (8 cols)
    const int ty = tid >> 5;   // row group (8 rows)

    float acc[8][8];
    #pragma unroll
    for (int r = 0; r < 8; r++)
        #pragma unroll
        for (int c = 0; c < 8; c++) acc[r][c] = 0.f;

    #pragma unroll 4
    for (int d1 = 0; d1 < 64; d1++) {
        float a[8];
        #pragma unroll
        for (int r = 0; r < 8; r++) a[r] = xs[d1 * 65 + ty * 8 + r];
        float4 w0 = reinterpret_cast<float4*>(ws + d1 * 256 + tx * 8)[0];
        float4 w1 = reinterpret_cast<float4*>(ws + d1 * 256 + tx * 8)[1];
        float wv[8] = {w0.x, w0.y, w0.z, w0.w, w1.x, w1.y, w1.z, w1.w};
        #pragma unroll
        for (int r = 0; r < 8; r++)
            #pragma unroll
            for (int c = 0; c < 8; c++) acc[r][c] += a[r] * wv[c];
    }

    #pragma unroll
    for (int r = 0; r < 8; r++) {
        float* dst = g_T + (rb * 64 + ty * 8 + r) * 4096 + cb * 256 + tx * 8;
        reinterpret_cast<float4*>(dst)[0] =
            make_float4(acc[r][0], acc[r][1], acc[r][2], acc[r][3]);
        reinterpret_cast<float4*>(dst)[1] =
            make_float4(acc[r][4], acc[r][5], acc[r][6], acc[r][7]);
    }
}

// ---------------------------------------------------------------------------
// Stage D: out[row, j, o] = sum_d2 T[row][d2][o] * Y[b][j][d2] + bc[o]
// Block = (row, j-tile of 128). 128 threads, 8j x 8o per thread.
// ---------------------------------------------------------------------------
__global__ void __launch_bounds__(128) out_kernel(const float* __restrict__ bc,
                                                  float* __restrict__ out)
{
    extern __shared__ float smem[];
    float* ts = smem;               // [64 d2][64 o]
    float* ys = smem + 64 * 64;     // [64 d2][132 j]
    const int YS = 132;

    const int blk = blockIdx.x;      // 0..8191
    const int jt  = blk & 3;         // j tile
    const int row = blk >> 2;        // b*512 + i
    const int b   = row >> 9;
    const int tid = threadIdx.x;

    // T_i straight copy (already [d2][o])
    {
        const float4* src = reinterpret_cast<const float4*>(g_T + row * 4096);
        float4* dst = reinterpret_cast<float4*>(ts);
        #pragma unroll
        for (int it = 0; it < 8; it++) dst[it * 128 + tid] = src[it * 128 + tid];
    }
    // Y tile transposed: thread tid owns local row j=tid -> conflict-free STS
    {
        const float4* src =
            reinterpret_cast<const float4*>(g_Y + (b * 512 + jt * 128 + tid) * 64);
        #pragma unroll
        for (int c4 = 0; c4 < 16; c4++) {
            float4 v = src[c4];
            ys[(4 * c4 + 0) * YS + tid] = v.x;
            ys[(4 * c4 + 1) * YS + tid] = v.y;
            ys[(4 * c4 + 2) * YS + tid] = v.z;
            ys[(4 * c4 + 3) * YS + tid] = v.w;
        }
    }
    __syncthreads();

    const int tx = tid & 7;    // o group (8 o)
    const int ty = tid >> 3;   // j group (8 j), 16 groups

    float acc[8][8];
    #pragma unroll
    for (int r = 0; r < 8; r++)
        #pragma unroll
        for (int c = 0; c < 8; c++) acc[r][c] = 0.f;

    #pragma unroll 4
    for (int d2 = 0; d2 < 64; d2++) {
        float4 t0 = reinterpret_cast<float4*>(ts + d2 * 64 + tx * 8)[0];
        float4 t1 = reinterpret_cast<float4*>(ts + d2 * 64 + tx * 8)[1];
        float4 y0 = reinterpret_cast<float4*>(ys + d2 * YS + ty * 8)[0];
        float4 y1 = reinterpret_cast<float4*>(ys + d2 * YS + ty * 8)[1];
        float tv[8] = {t0.x, t0.y, t0.z, t0.w, t1.x, t1.y, t1.z, t1.w};
        float yv[8] = {y0.x, y0.y, y0.z, y0.w, y1.x, y1.y, y1.z, y1.w};
        #pragma unroll
        for (int r = 0; r < 8; r++)
            #pragma unroll
            for (int c = 0; c < 8; c++) acc[r][c] += yv[r] * tv[c];
    }

    float bco[8];
    #pragma unroll
    for (int c = 0; c < 8; c++) bco[c] = bc[tx * 8 + c];

    #pragma unroll
    for (int r = 0; r < 8; r++) {
        int j = jt * 128 + ty * 8 + r;
        float* dst = out + (row * 512 + j) * 64 + tx * 8;
        reinterpret_cast<float4*>(dst)[0] =
            make_float4(acc[r][0] + bco[0], acc[r][1] + bco[1],
                        acc[r][2] + bco[2], acc[r][3] + bco[3]);
        reinterpret_cast<float4*>(dst)[1] =
            make_float4(acc[r][4] + bco[4], acc[r][5] + bco[5],
                        acc[r][6] + bco[6], acc[r][7] + bco[7]);
    }
}

// ---------------------------------------------------------------------------
extern "C" void kernel_launch(void* const* d_in, const int* in_sizes, int n_in,
                              void* d_out, int out_size)
{
    const float* emb  = (const float*)d_in[0];
    /* d_in[1] = node_mask, unused */
    const float* ln_g = (const float*)d_in[2];
    const float* ln_b = (const float*)d_in[3];
    const float* W1   = (const float*)d_in[4];
    const float* b1   = (const float*)d_in[5];
    const float* W2   = (const float*)d_in[6];
    const float* b2   = (const float*)d_in[7];
    const float* Wc   = (const float*)d_in[8];
    const float* bc   = (const float*)d_in[9];
    float* out = (float*)d_out;

    const int smemB = (64 * 65 + 64 * 256) * sizeof(float);   // 82176
    const int smemD = (64 * 64 + 64 * 132) * sizeof(float);   // 50176
    cudaFuncSetAttribute(t_kernel,   cudaFuncAttributeMaxDynamicSharedMemorySize, smemB);
    cudaFuncSetAttribute(out_kernel, cudaFuncAttributeMaxDynamicSharedMemorySize, smemD);

    prep_kernel<<<NROWS, 64>>>(emb, ln_g, ln_b, W1, b1, W2, b2);
    wt_kernel<<<(EDIM * CDIM) / 256, 256>>>(Wc);
    {
        dim3 grid(16, 32);      // 16 col blocks x 32 row blocks
        t_kernel<<<grid, 256, smemB>>>();
    }
    out_kernel<<<NROWS * 4, 128, smemD>>>(bc, out);
}

// round 9
// speedup vs baseline: 1.1371x; 1.1371x over previous
#include <cuda_runtime.h>

// Problem constants: B=4, N=512, E=64
#define NROWS 2048          // B*N
#define EDIM  64
#define CDIM  4096          // E*E

// Scratch (static device allocations are allowed)
__device__ float g_X[NROWS * EDIM];          // left gated activations  [row][d1]
__device__ float g_Y[NROWS * EDIM];          // right gated activations [row][d2]
__device__ float g_Wt[EDIM * CDIM];          // Wt[d1][d2*64+o] = Wc[o][d1*64+d2]
__device__ float g_T[NROWS * CDIM];          // T[row][d2*64+o]

// ---------------------------------------------------------------------------
// Packed fp32x2 helpers (Blackwell packed FMA — 2x scalar FFMA throughput)
// ---------------------------------------------------------------------------
__device__ __forceinline__ unsigned long long bcast2(float x) {
    unsigned long long r;
    asm("mov.b64 %0, {%1, %1};" : "=l"(r) : "f"(x));
    return r;
}
__device__ __forceinline__ void fma2(unsigned long long& d,
                                     unsigned long long a,
                                     unsigned long long b) {
    asm("fma.rn.f32x2 %0, %1, %2, %3;" : "=l"(d) : "l"(a), "l"(b), "l"(d));
}
__device__ __forceinline__ float2 unpk(unsigned long long v) {
    float2 f;
    asm("mov.b64 {%0, %1}, %2;" : "=f"(f.x), "=f"(f.y) : "l"(v));
    return f;
}

// ---------------------------------------------------------------------------
// Stage A: LayerNorm + two gated projections. 1 block per row, 64 threads.
// ---------------------------------------------------------------------------
__global__ void prep_kernel(const float* __restrict__ emb,
                            const float* __restrict__ g,
                            const float* __restrict__ be,
                            const float* __restrict__ W1,
                            const float* __restrict__ b1,
                            const float* __restrict__ W2,
                            const float* __restrict__ b2)
{
    __shared__ float hsh[64];
    __shared__ float w1s[64 * 65];   // transposed [d][o], pad 65 -> conflict free
    __shared__ float w2s[64 * 65];

    const int row = blockIdx.x;
    const int t   = threadIdx.x;

    for (int i = 0; i < 64; i++) {
        w1s[t * 65 + i] = W1[i * 64 + t];   // w1s[d=t][o=i]
        w2s[t * 65 + i] = W2[i * 64 + t];
    }

    float v = emb[row * 64 + t];
    hsh[t] = v;
    __syncthreads();

    float s = 0.f;
    #pragma unroll
    for (int d = 0; d < 64; d++) s += hsh[d];
    float mu = s * (1.0f / 64.0f);

    float vs = 0.f;
    #pragma unroll
    for (int d = 0; d < 64; d++) { float z = hsh[d] - mu; vs += z * z; }
    float rstd = rsqrtf(vs * (1.0f / 64.0f) + 1e-5f);

    float h = (v - mu) * rstd * g[t] + be[t];
    __syncthreads();
    hsh[t] = h;
    __syncthreads();

    float p1 = b1[t], p2 = b2[t];
    #pragma unroll
    for (int d = 0; d < 64; d++) {
        float hd = hsh[d];
        p1 += hd * w1s[d * 65 + t];
        p2 += hd * w2s[d * 65 + t];
    }
    g_X[row * 64 + t] = h * p1;
    g_Y[row * 64 + t] = h * p2;
}

// ---------------------------------------------------------------------------
// Stage C: transpose Wc into Wt[d1*4096 + d2*64 + o] = Wc[o*4096 + d1*64 + d2]
// ---------------------------------------------------------------------------
__global__ void wt_kernel(const float* __restrict__ Wc)
{
    int i = blockIdx.x * blockDim.x + threadIdx.x;   // 0 .. 262143
    int o    = i & 63;
    int rest = i >> 6;          // d1*64 + d2
    g_Wt[i] = Wc[o * 4096 + rest];
}

// ---------------------------------------------------------------------------
// Stage B: T = X @ Wt    ([2048 x 64] * [64 x 4096])
// Block tile 64 rows x 256 cols, 256 threads, 8 rows x 8 cols per thread
// (cols in two chunks of 4: c = tx*4+k and 128+tx*4+k  -> conflict-free LDS.128).
// Packed f32x2 accumulation.
// ---------------------------------------------------------------------------
__global__ void __launch_bounds__(256) t_kernel()
{
    extern __shared__ float smem[];
    float* xs = smem;             // [64 d1][64 r]  (rows transposed, no pad)
    float* ws = smem + 64 * 64;   // [64 d1][256 c]

    const int cb  = blockIdx.x;   // 0..15 (col block of 256)
    const int rb  = blockIdx.y;   // 0..31 (row block of 64)
    const int tid = threadIdx.x;

    // Fill xs transposed: threads 0..63 each own one local row (conflict-free STS)
    if (tid < 64) {
        const float4* src = reinterpret_cast<const float4*>(g_X + (rb * 64 + tid) * 64);
        #pragma unroll
        for (int c4 = 0; c4 < 16; c4++) {
            float4 v = src[c4];
            xs[(4 * c4 + 0) * 64 + tid] = v.x;
            xs[(4 * c4 + 1) * 64 + tid] = v.y;
            xs[(4 * c4 + 2) * 64 + tid] = v.z;
            xs[(4 * c4 + 3) * 64 + tid] = v.w;
        }
    }
    // Fill ws straight: ws[d1][c], 4096 float4s
    #pragma unroll
    for (int it = 0; it < 16; it++) {
        int idx = it * 256 + tid;         // 0..4095
        int d1  = idx >> 6;
        int c4  = idx & 63;
        reinterpret_cast<float4*>(ws + d1 * 256)[c4] =
            reinterpret_cast<const float4*>(g_Wt + d1 * 4096 + cb * 256)[c4];
    }
    __syncthreads();

    const int tx = tid & 31;   // col group: cols tx*4+k (lo) and 128+tx*4+k (hi)
    const int ty = tid >> 5;   // row group (8 rows), constant within warp

    unsigned long long acc[8][4];        // [row][pair]: pairs 0,1 = lo chunk, 2,3 = hi
    #pragma unroll
    for (int r = 0; r < 8; r++)
        #pragma unroll
        for (int p = 0; p < 4; p++) acc[r][p] = 0ull;

    #pragma unroll 4
    for (int d1 = 0; d1 < 64; d1++) {
        const float* xrow = xs + d1 * 64 + ty * 8;
        float4 a0 = reinterpret_cast<const float4*>(xrow)[0];  // broadcast (whole warp)
        float4 a1 = reinterpret_cast<const float4*>(xrow)[1];
        const float* wrow = ws + d1 * 256;
        ulonglong2 wA = *reinterpret_cast<const ulonglong2*>(wrow + tx * 4);        // lo
        ulonglong2 wB = *reinterpret_cast<const ulonglong2*>(wrow + 128 + tx * 4);  // hi
        unsigned long long tv[4] = {wA.x, wA.y, wB.x, wB.y};
        float av[8] = {a0.x, a0.y, a0.z, a0.w, a1.x, a1.y, a1.z, a1.w};
        #pragma unroll
        for (int r = 0; r < 8; r++) {
            unsigned long long yb = bcast2(av[r]);
            #pragma unroll
            for (int p = 0; p < 4; p++) fma2(acc[r][p], yb, tv[p]);
        }
    }

    #pragma unroll
    for (int r = 0; r < 8; r++) {
        float* dst = g_T + (rb * 64 + ty * 8 + r) * 4096 + cb * 256;
        float2 a0 = unpk(acc[r][0]), a1 = unpk(acc[r][1]);
        float2 a2 = unpk(acc[r][2]), a3 = unpk(acc[r][3]);
        reinterpret_cast<float4*>(dst + tx * 4)[0] =
            make_float4(a0.x, a0.y, a1.x, a1.y);
        reinterpret_cast<float4*>(dst + 128 + tx * 4)[0] =
            make_float4(a2.x, a2.y, a3.x, a3.y);
    }
}

// ---------------------------------------------------------------------------
// Stage D: out[row, j, o] = sum_d2 T[row][d2][o] * Y[b][j][d2] + bc[o]
// Block = (row, j-tile of 256). 128 threads, 16j x 8o per thread.
// o in two chunks of 4 (tx*4 and 32+tx*4), j in four chunks of 4 (c*64 + ty*4).
// Packed f32x2 accumulation.
// ---------------------------------------------------------------------------
__global__ void __launch_bounds__(128) out_kernel(const float* __restrict__ bc,
                                                  float* __restrict__ out)
{
    extern __shared__ float smem[];
    float* ts = smem;               // [64 d2][64 o]
    float* ys = smem + 64 * 64;     // [64 d2][256 j]

    const int blk = blockIdx.x;      // 0..4095
    const int jt  = blk & 1;         // j tile (256 each)
    const int row = blk >> 1;        // b*512 + i
    const int b   = row >> 9;
    const int tid = threadIdx.x;

    // T_i straight copy (already [d2][o])
    {
        const float4* src = reinterpret_cast<const float4*>(g_T + row * 4096);
        float4* dst = reinterpret_cast<float4*>(ts);
        #pragma unroll
        for (int it = 0; it < 8; it++) dst[it * 128 + tid] = src[it * 128 + tid];
    }
    // Y tile transposed: thread owns local rows tid and tid+128 (conflict-free STS)
    #pragma unroll
    for (int h = 0; h < 2; h++) {
        int jr = tid + h * 128;
        const float4* src =
            reinterpret_cast<const float4*>(g_Y + (b * 512 + jt * 256 + jr) * 64);
        #pragma unroll
        for (int c4 = 0; c4 < 16; c4++) {
            float4 v = src[c4];
            ys[(4 * c4 + 0) * 256 + jr] = v.x;
            ys[(4 * c4 + 1) * 256 + jr] = v.y;
            ys[(4 * c4 + 2) * 256 + jr] = v.z;
            ys[(4 * c4 + 3) * 256 + jr] = v.w;
        }
    }
    __syncthreads();

    const int tx = tid & 7;    // o group: o = tx*4+k (lo), 32+tx*4+k (hi)
    const int ty = tid >> 3;   // j group (16 groups of 4, x4 chunks of 64)

    unsigned long long acc[4][4][4];   // [jchunk][jr][pair]
    #pragma unroll
    for (int c = 0; c < 4; c++)
        #pragma unroll
        for (int r = 0; r < 4; r++)
            #pragma unroll
            for (int p = 0; p < 4; p++) acc[c][r][p] = 0ull;

    #pragma unroll 2
    for (int d2 = 0; d2 < 64; d2++) {
        const float* tsrow = ts + d2 * 64;
        ulonglong2 tA = *reinterpret_cast<const ulonglong2*>(tsrow + tx * 4);       // o lo
        ulonglong2 tB = *reinterpret_cast<const ulonglong2*>(tsrow + 32 + tx * 4);  // o hi
        unsigned long long tv[4] = {tA.x, tA.y, tB.x, tB.y};
        const float* ysrow = ys + d2 * 256 + ty * 4;
        #pragma unroll
        for (int c = 0; c < 4; c++) {
            float4 yq = *reinterpret_cast<const float4*>(ysrow + c * 64);
            unsigned long long y0 = bcast2(yq.x);
            unsigned long long y1 = bcast2(yq.y);
            unsigned long long y2 = bcast2(yq.z);
            unsigned long long y3 = bcast2(yq.w);
            #pragma unroll
            for (int p = 0; p < 4; p++) {
                fma2(acc[c][0][p], y0, tv[p]);
                fma2(acc[c][1][p], y1, tv[p]);
                fma2(acc[c][2][p], y2, tv[p]);
                fma2(acc[c][3][p], y3, tv[p]);
            }
        }
    }

    float bl[4], bh[4];
    #pragma unroll
    for (int k = 0; k < 4; k++) { bl[k] = bc[tx * 4 + k]; bh[k] = bc[32 + tx * 4 + k]; }

    #pragma unroll
    for (int c = 0; c < 4; c++) {
        #pragma unroll
        for (int r = 0; r < 4; r++) {
            int j = jt * 256 + c * 64 + ty * 4 + r;
            float* dst = out + ((long long)(row) * 512 + j) * 64;
            float2 a0 = unpk(acc[c][r][0]), a1 = unpk(acc[c][r][1]);
            float2 a2 = unpk(acc[c][r][2]), a3 = unpk(acc[c][r][3]);
            reinterpret_cast<float4*>(dst + tx * 4)[0] =
                make_float4(a0.x + bl[0], a0.y + bl[1], a1.x + bl[2], a1.y + bl[3]);
            reinterpret_cast<float4*>(dst + 32 + tx * 4)[0] =
                make_float4(a2.x + bh[0], a2.y + bh[1], a3.x + bh[2], a3.y + bh[3]);
        }
    }
}

// ---------------------------------------------------------------------------
extern "C" void kernel_launch(void* const* d_in, const int* in_sizes, int n_in,
                              void* d_out, int out_size)
{
    const float* emb  = (const float*)d_in[0];
    /* d_in[1] = node_mask, unused */
    const float* ln_g = (const float*)d_in[2];
    const float* ln_b = (const float*)d_in[3];
    const float* W1   = (const float*)d_in[4];
    const float* b1   = (const float*)d_in[5];
    const float* W2   = (const float*)d_in[6];
    const float* b2   = (const float*)d_in[7];
    const float* Wc   = (const float*)d_in[8];
    const float* bc   = (const float*)d_in[9];
    float* out = (float*)d_out;

    const int smemB = (64 * 64 + 64 * 256) * sizeof(float);   // 81920
    const int smemD = (64 * 64 + 64 * 256) * sizeof(float);   // 81920
    cudaFuncSetAttribute(t_kernel,   cudaFuncAttributeMaxDynamicSharedMemorySize, smemB);
    cudaFuncSetAttribute(out_kernel, cudaFuncAttributeMaxDynamicSharedMemorySize, smemD);

    prep_kernel<<<NROWS, 64>>>(emb, ln_g, ln_b, W1, b1, W2, b2);
    wt_kernel<<<(EDIM * CDIM) / 256, 256>>>(Wc);
    {
        dim3 grid(16, 32);      // 16 col blocks x 32 row blocks
        t_kernel<<<grid, 256, smemB>>>();
    }
    out_kernel<<<NROWS * 2, 128, smemD>>>(bc, out);
}